// round 12
// baseline (speedup 1.0000x reference)
#include <cuda_runtime.h>
#include <cuda_fp16.h>
#include <cstdint>

#define N_NODES 50000
#define N_EDGES 800000
#define KDIM    256
#define H_DIM   256
#define L_DIM   128
#define EPS_BN  1e-5f

// ---------------- scratch (device globals; no allocations allowed) ----------
__device__ __align__(16) __half g_hH[(size_t)N_NODES * H_DIM];   // GEMM half outputs
__device__ __align__(16) __half g_yH[(size_t)N_NODES * H_DIM];   // SpMM half outputs
__device__ __align__(16) __half g_W1h[KDIM * H_DIM];
__device__ __align__(16) __half g_W2h[KDIM * H_DIM];
__device__ __align__(16) __half g_Wfh[KDIM * L_DIM];
__device__ int      g_cnt[N_NODES + 1];
__device__ int      g_rowptr[N_NODES + 1];
__device__ int      g_ofs[N_NODES];
__device__ __align__(8) int2 g_epack[N_EDGES];   // (col, val bits)
__device__ double   g_stats[2][2 * H_DIM];       // per-layer [sum | sumsq]
__device__ unsigned g_done[2];                   // per-layer finalize counters
__device__ __align__(16) float g_a1[H_DIM];
__device__ __align__(16) float g_c1[H_DIM];
__device__ __align__(16) float g_a2[H_DIM];
__device__ __align__(16) float g_c2[H_DIM];

// ---------------- helpers ----------------------------------------------------
__device__ __forceinline__ uint32_t smem_u32(const void* p) {
    uint32_t a;
    asm("{ .reg .u64 t; cvta.to.shared.u64 t, %1; cvt.u32.u64 %0, t; }"
        : "=r"(a) : "l"(p));
    return a;
}

__device__ __forceinline__ uint32_t pack_h2(float a, float b) {
    __half2 h = __floats2half2_rn(a, b);
    return *reinterpret_cast<uint32_t*>(&h);
}

// ---------------- weight convert fp32 -> fp16 + cnt zero ---------------------
__global__ void cvt_weights(const float* __restrict__ W1,
                            const float* __restrict__ W2,
                            const float* __restrict__ Wf) {
    const int i = blockIdx.x * blockDim.x + threadIdx.x;
    constexpr int S1 = KDIM * H_DIM;
    constexpr int S2 = 2 * S1;
    constexpr int S3 = S2 + KDIM * L_DIM;
    if (i < S1)      g_W1h[i]      = __float2half_rn(W1[i]);
    else if (i < S2) g_W2h[i - S1] = __float2half_rn(W2[i - S1]);
    else if (i < S3) g_Wfh[i - S2] = __float2half_rn(Wf[i - S2]);
    if (i <= N_NODES) g_cnt[i] = 0;              // CSR histogram zero (pre-fork)
}

// ---------------- CSR build --------------------------------------------------
__global__ void hist_kernel(const int* __restrict__ rows, int E) {
    int i = blockIdx.x * blockDim.x + threadIdx.x;
    if (i < E) atomicAdd(&g_cnt[rows[i]], 1);
}

__global__ void scan_kernel() {
    __shared__ int part[1024];
    const int t = threadIdx.x;
    // zero BN stats + finalize counters for this replay
    ((double*)g_stats)[t] = 0.0;
    if (t < 2) g_done[t] = 0u;
    const int CH = (N_NODES + 1023) / 1024;
    const int base = t * CH;
    int local = 0;
    for (int i = 0; i < CH; i++) {
        int r = base + i;
        if (r < N_NODES) local += g_cnt[r];
    }
    part[t] = local;
    __syncthreads();
    for (int off = 1; off < 1024; off <<= 1) {
        int v = (t >= off) ? part[t - off] : 0;
        __syncthreads();
        part[t] += v;
        __syncthreads();
    }
    int incl = part[t];
    int run = incl - local;
    for (int i = 0; i < CH; i++) {
        int r = base + i;
        if (r < N_NODES) {
            g_rowptr[r] = run;
            g_ofs[r]    = run;
            run += g_cnt[r];
        }
    }
    if (t == 1023) g_rowptr[N_NODES] = incl;
}

__global__ void scatter_kernel(const int* __restrict__ rows,
                               const int* __restrict__ cols,
                               const float* __restrict__ vals, int E) {
    int i = blockIdx.x * blockDim.x + threadIdx.x;
    if (i < E) {
        int p = atomicAdd(&g_ofs[rows[i]], 1);
        g_epack[p] = make_int2(cols[i], __float_as_int(vals[i]));
    }
}

// ---------------- SpMM (half gather, half out) + fused BN stats + finalize ---
__device__ __forceinline__ void accum8(float* acc, uint4 u, float v) {
    const __half2* h = reinterpret_cast<const __half2*>(&u);
    #pragma unroll
    for (int j = 0; j < 4; j++) {
        float2 f = __half22float2(h[j]);
        acc[2 * j]     += v * f.x;
        acc[2 * j + 1] += v * f.y;
    }
}

template<int LAYER>
__global__ __launch_bounds__(256)
void spmm_stats_kernel(const __half* __restrict__ x, __half* __restrict__ y,
                       const float* __restrict__ gamma, const float* __restrict__ beta,
                       float* __restrict__ oa, float* __restrict__ oc) {
    __shared__ float ss[8][H_DIM];
    __shared__ float sq[8][H_DIM];
    const int tid  = threadIdx.x;
    const int wid  = tid >> 5;
    const int lane = tid & 31;
    float s[8] = {}, q[8] = {};

    for (int r = 0; r < 4; r++) {
        const int row = blockIdx.x * 32 + wid * 4 + r;
        if (row < N_NODES) {
            int p = g_rowptr[row];
            const int e = g_rowptr[row + 1];
            float acc[8] = {};
            for (; p + 4 <= e; p += 4) {
                const int2 e0 = __ldg(&g_epack[p]);
                const int2 e1 = __ldg(&g_epack[p + 1]);
                const int2 e2 = __ldg(&g_epack[p + 2]);
                const int2 e3 = __ldg(&g_epack[p + 3]);
                uint4 u0 = __ldg(reinterpret_cast<const uint4*>(x + (size_t)e0.x * H_DIM) + lane);
                uint4 u1 = __ldg(reinterpret_cast<const uint4*>(x + (size_t)e1.x * H_DIM) + lane);
                uint4 u2 = __ldg(reinterpret_cast<const uint4*>(x + (size_t)e2.x * H_DIM) + lane);
                uint4 u3 = __ldg(reinterpret_cast<const uint4*>(x + (size_t)e3.x * H_DIM) + lane);
                accum8(acc, u0, __int_as_float(e0.y));
                accum8(acc, u1, __int_as_float(e1.y));
                accum8(acc, u2, __int_as_float(e2.y));
                accum8(acc, u3, __int_as_float(e3.y));
            }
            for (; p < e; p++) {
                const int2 e0 = __ldg(&g_epack[p]);
                uint4 u0 = __ldg(reinterpret_cast<const uint4*>(x + (size_t)e0.x * H_DIM) + lane);
                accum8(acc, u0, __int_as_float(e0.y));
            }
            uint4 o;
            __half2* oh = reinterpret_cast<__half2*>(&o);
            oh[0] = __floats2half2_rn(acc[0], acc[1]);
            oh[1] = __floats2half2_rn(acc[2], acc[3]);
            oh[2] = __floats2half2_rn(acc[4], acc[5]);
            oh[3] = __floats2half2_rn(acc[6], acc[7]);
            *reinterpret_cast<uint4*>(y + (size_t)row * H_DIM + lane * 8) = o;
            #pragma unroll
            for (int j = 0; j < 8; j++) { s[j] += acc[j]; q[j] += acc[j] * acc[j]; }
        }
    }

    #pragma unroll
    for (int j = 0; j < 8; j++) {
        ss[wid][lane * 8 + j] = s[j];
        sq[wid][lane * 8 + j] = q[j];
    }
    __syncthreads();
    const int ch = tid;
    float S = 0.f, Q = 0.f;
    #pragma unroll
    for (int w = 0; w < 8; w++) { S += ss[w][ch]; Q += sq[w][ch]; }
    double* st = g_stats[LAYER];
    atomicAdd(&st[ch], (double)S);
    atomicAdd(&st[H_DIM + ch], (double)Q);

    // ---- last-block finalize: compute per-channel a, c ----
    __shared__ unsigned s_last;
    __threadfence();
    if (tid == 0) s_last = (atomicAdd(&g_done[LAYER], 1u) == gridDim.x - 1u) ? 1u : 0u;
    __syncthreads();
    if (s_last) {
        __threadfence();
        double sv = *((volatile double*)&st[ch]);
        double qv = *((volatile double*)&st[H_DIM + ch]);
        float mean = (float)(sv / N_NODES);
        float var  = (float)(qv / N_NODES) - mean * mean;
        float rstd = rsqrtf(var + EPS_BN);
        float a = gamma[ch] * rstd;
        oa[ch] = a;
        oc[ch] = beta[ch] - mean * a;
    }
}

// ---------------- fp16 tensor-core GEMM --------------------------------------
// C[M, GN] = op(A)[M, 256] @ Bh[256, GN];  A is fp32 or fp16 (template AT)
//   FUSE_BN: A col k -> relu(x*bna[k]+bnc[k]) before half convert
//   GATHER : A row m read from A[gidx[m]]
template<int GN, bool FUSE_BN, bool GATHER, bool BIAS, bool OUT_HALF, typename AT>
__global__ __launch_bounds__(256, 2)
void hgemm(const AT* __restrict__ A, const __half* __restrict__ Bh,
           const float* __restrict__ bias, void* __restrict__ Cptr,
           int M, const int* __restrict__ gidx,
           const float* __restrict__ bna, const float* __restrict__ bnc) {
    constexpr int ASTR = 80;
    constexpr int ASZ  = 128 * ASTR;
    constexpr int BSZ  = 32 * 256;
    __shared__ __align__(16) char sAm[2 * ASZ];
    __shared__ __align__(16) char sBm[2 * BSZ];
    const uint32_t sAu = smem_u32(sAm);
    const uint32_t sBu = smem_u32(sBm);

    const int tid  = threadIdx.x;
    const int lane = tid & 31;
    const int wid  = tid >> 5;
    const int wm   = wid & 1;
    const int wn   = wid >> 1;
    const int g    = lane >> 2;
    const int t4   = lane & 3;
    const int lrow = lane & 15;
    const int lko  = (lane >> 4) << 4;
    const int row0 = blockIdx.y * 128;
    const int col0 = blockIdx.x * 128;

    const int am = tid >> 1;                 // A staging row 0..127
    const int ak = tid & 1;                  // which 16-k half of 32-k chunk

    float4 af[4];                            // fp32 A raw (float path)
    uint4  ah[2];                            // fp16 A raw (half path)
    float acc[4][4][4];
    #pragma unroll
    for (int i = 0; i < 4; i++)
        #pragma unroll
        for (int j = 0; j < 4; j++)
            #pragma unroll
            for (int k = 0; k < 4; k++) acc[i][j][k] = 0.f;

    auto ldgA = [&](int c) {
        const int gm = row0 + am;
        const int k0 = c * 32 + ak * 16;
        if (gm < M) {
            const int src = GATHER ? __ldg(&gidx[gm]) : gm;
            if constexpr (sizeof(AT) == 4) {
                const float4* p = reinterpret_cast<const float4*>(
                    (const float*)A + (size_t)src * KDIM + k0);
                af[0] = p[0]; af[1] = p[1]; af[2] = p[2]; af[3] = p[3];
            } else {
                const uint4* p = reinterpret_cast<const uint4*>(
                    (const __half*)A + (size_t)src * KDIM + k0);
                ah[0] = p[0]; ah[1] = p[1];
            }
        } else {
            if constexpr (sizeof(AT) == 4) {
                af[0] = af[1] = af[2] = af[3] = make_float4(0.f, 0.f, 0.f, 0.f);
            } else {
                ah[0] = ah[1] = make_uint4(0u, 0u, 0u, 0u);
            }
        }
    };

    auto stsA = [&](int c, int buf) {
        const int k0 = c * 32 + ak * 16;
        float v[16];
        if constexpr (sizeof(AT) == 4) {
            *reinterpret_cast<float4*>(v)      = af[0];
            *reinterpret_cast<float4*>(v + 4)  = af[1];
            *reinterpret_cast<float4*>(v + 8)  = af[2];
            *reinterpret_cast<float4*>(v + 12) = af[3];
        } else {
            const __half2* hp = reinterpret_cast<const __half2*>(ah);
            #pragma unroll
            for (int j = 0; j < 8; j++) {
                float2 f = __half22float2(hp[j]);
                v[2 * j] = f.x; v[2 * j + 1] = f.y;
            }
        }
        if (FUSE_BN) {
            #pragma unroll
            for (int q2 = 0; q2 < 4; q2++) {
                float4 aa = *reinterpret_cast<const float4*>(bna + k0 + q2 * 4);
                float4 cc = *reinterpret_cast<const float4*>(bnc + k0 + q2 * 4);
                float* vp = v + q2 * 4;
                vp[0] = fmaxf(vp[0] * aa.x + cc.x, 0.f);
                vp[1] = fmaxf(vp[1] * aa.y + cc.y, 0.f);
                vp[2] = fmaxf(vp[2] * aa.z + cc.z, 0.f);
                vp[3] = fmaxf(vp[3] * aa.w + cc.w, 0.f);
            }
        }
        uint32_t h[8];
        #pragma unroll
        for (int j = 0; j < 8; j++) h[j] = pack_h2(v[2 * j], v[2 * j + 1]);
        char* dst = sAm + buf * ASZ + am * ASTR + ak * 32;
        *reinterpret_cast<uint4*>(dst)      = make_uint4(h[0], h[1], h[2], h[3]);
        *reinterpret_cast<uint4*>(dst + 16) = make_uint4(h[4], h[5], h[6], h[7]);
    };

    auto stageB = [&](int c, int buf) {
        const uint32_t base = sBu + buf * BSZ;
        const __half* src = Bh + (size_t)(c * 32) * GN + col0;
        #pragma unroll
        for (int i = 0; i < 2; i++) {
            const int id = tid + i * 256;
            const int kk = id >> 4, cc = id & 15;
            const uint32_t dst = base + kk * 256 + ((cc ^ (kk & 7)) << 4);
            const void* gp = src + (size_t)kk * GN + cc * 8;
            asm volatile("cp.async.ca.shared.global [%0], [%1], 16;\n"
                         :: "r"(dst), "l"(gp));
        }
        asm volatile("cp.async.commit_group;\n" ::: "memory");
    };

    auto compute = [&](int buf) {
        const uint32_t aB = sAu + buf * ASZ;
        const uint32_t bB = sBu + buf * BSZ;
        #pragma unroll
        for (int kb = 0; kb < 32; kb += 16) {
            uint32_t a[4][4];
            #pragma unroll
            for (int mf = 0; mf < 4; mf++) {
                const int m0 = wm * 64 + mf * 16;
                const uint32_t ad = aB + (uint32_t)(m0 + lrow) * ASTR + kb * 2 + lko;
                asm volatile("ldmatrix.sync.aligned.m8n8.x4.shared.b16 {%0,%1,%2,%3}, [%4];"
                             : "=r"(a[mf][0]), "=r"(a[mf][1]), "=r"(a[mf][2]), "=r"(a[mf][3])
                             : "r"(ad));
            }
            uint32_t b[4][2];
            #pragma unroll
            for (int pr = 0; pr < 2; pr++) {
                const int n0 = wn * 32 + pr * 16;
                const int rk = kb + lrow;
                const int ch = (n0 >> 3) + (lane >> 4);
                const uint32_t bd = bB + (uint32_t)rk * 256 + ((ch ^ (rk & 7)) << 4);
                uint32_t r0, r1, r2, r3;
                asm volatile("ldmatrix.sync.aligned.m8n8.x4.trans.shared.b16 {%0,%1,%2,%3}, [%4];"
                             : "=r"(r0), "=r"(r1), "=r"(r2), "=r"(r3) : "r"(bd));
                b[pr * 2][0] = r0; b[pr * 2][1] = r1;
                b[pr * 2 + 1][0] = r2; b[pr * 2 + 1][1] = r3;
            }
            #pragma unroll
            for (int mf = 0; mf < 4; mf++)
                #pragma unroll
                for (int nf = 0; nf < 4; nf++)
                    asm volatile(
                        "mma.sync.aligned.m16n8k16.row.col.f32.f16.f16.f32 "
                        "{%0,%1,%2,%3}, {%4,%5,%6,%7}, {%8,%9}, {%0,%1,%2,%3};"
                        : "+f"(acc[mf][nf][0]), "+f"(acc[mf][nf][1]),
                          "+f"(acc[mf][nf][2]), "+f"(acc[mf][nf][3])
                        : "r"(a[mf][0]), "r"(a[mf][1]), "r"(a[mf][2]), "r"(a[mf][3]),
                          "r"(b[nf][0]), "r"(b[nf][1]));
        }
    };

    constexpr int NCH = KDIM / 32;   // 8 chunks
    stageB(0, 0);
    ldgA(0);
    stsA(0, 0);
    ldgA(1);

    for (int c = 0; c < NCH; c++) {
        const int buf = c & 1;
        asm volatile("cp.async.wait_group 0;\n" ::: "memory");
        __syncthreads();
        if (c + 1 < NCH) stageB(c + 1, buf ^ 1);
        compute(buf);
        if (c + 1 < NCH) {
            stsA(c + 1, buf ^ 1);
            if (c + 2 < NCH) ldgA(c + 2);
        }
    }

    // ---- epilogue ----
    #pragma unroll
    for (int mf = 0; mf < 4; mf++) {
        const int r = row0 + wm * 64 + mf * 16 + g;
        #pragma unroll
        for (int nf = 0; nf < 4; nf++) {
            const int cb = col0 + wn * 32 + nf * 8 + t4 * 2;
            float b0 = 0.f, b1 = 0.f;
            if (BIAS) { b0 = __ldg(&bias[cb]); b1 = __ldg(&bias[cb + 1]); }
            if (OUT_HALF) {
                __half* C = (__half*)Cptr;
                if (r < M) {
                    uint32_t h = pack_h2(acc[mf][nf][0] + b0, acc[mf][nf][1] + b1);
                    *reinterpret_cast<uint32_t*>(C + (size_t)r * GN + cb) = h;
                }
                if (r + 8 < M) {
                    uint32_t h = pack_h2(acc[mf][nf][2] + b0, acc[mf][nf][3] + b1);
                    *reinterpret_cast<uint32_t*>(C + (size_t)(r + 8) * GN + cb) = h;
                }
            } else {
                float* C = (float*)Cptr;
                if (r < M)
                    *reinterpret_cast<float2*>(C + (size_t)r * GN + cb) =
                        make_float2(acc[mf][nf][0] + b0, acc[mf][nf][1] + b1);
                if (r + 8 < M)
                    *reinterpret_cast<float2*>(C + (size_t)(r + 8) * GN + cb) =
                        make_float2(acc[mf][nf][2] + b0, acc[mf][nf][3] + b1);
            }
        }
    }
}

// ---------------- launch -----------------------------------------------------
extern "C" void kernel_launch(void* const* d_in, const int* in_sizes, int n_in,
                              void* d_out, int out_size) {
    const float* features  = (const float*)d_in[0];
    const float* edge_vals = (const float*)d_in[1];
    const float* W1        = (const float*)d_in[2];
    const float* db1       = (const float*)d_in[3];
    // d_in[4] = b1  (cancels inside BatchNorm, skipped)
    const float* g1        = (const float*)d_in[5];
    const float* be1       = (const float*)d_in[6];
    const float* W2        = (const float*)d_in[7];
    // d_in[8] = b2  (cancels inside BatchNorm, skipped)
    const float* g2        = (const float*)d_in[9];
    const float* be2       = (const float*)d_in[10];
    const float* Wf        = (const float*)d_in[11];
    const float* bf        = (const float*)d_in[12];
    const int*   edge_rows = (const int*)d_in[13];
    const int*   edge_cols = (const int*)d_in[14];
    const int*   idx       = (const int*)d_in[15];

    const int E  = in_sizes[1];
    const int Mi = in_sizes[15];
    float* out = (float*)d_out;

    __half *hH, *yH, *w1h, *w2h, *wfh;
    float *a1, *c1, *a2, *c2;
    cudaGetSymbolAddress((void**)&hH,  g_hH);
    cudaGetSymbolAddress((void**)&yH,  g_yH);
    cudaGetSymbolAddress((void**)&w1h, g_W1h);
    cudaGetSymbolAddress((void**)&w2h, g_W2h);
    cudaGetSymbolAddress((void**)&wfh, g_Wfh);
    cudaGetSymbolAddress((void**)&a1, g_a1);
    cudaGetSymbolAddress((void**)&c1, g_c1);
    cudaGetSymbolAddress((void**)&a2, g_a2);
    cudaGetSymbolAddress((void**)&c2, g_c2);

    cudaStream_t s2 = 0;
    cudaEvent_t eFork = nullptr, eJoin = nullptr;
    bool forked = (cudaStreamCreateWithFlags(&s2, cudaStreamNonBlocking) == cudaSuccess) &&
                  (cudaEventCreateWithFlags(&eFork, cudaEventDisableTiming) == cudaSuccess) &&
                  (cudaEventCreateWithFlags(&eJoin, cudaEventDisableTiming) == cudaSuccess);
    cudaStream_t sb = forked ? s2 : 0;

    // (1) weights fp16 + zero CSR histogram (main stream, before fork)
    cvt_weights<<<(2 * KDIM * H_DIM + KDIM * L_DIM + 255) / 256, 256>>>(W1, W2, Wf);

    if (forked) {
        cudaEventRecord(eFork, 0);
        cudaStreamWaitEvent(s2, eFork, 0);
    }

    // (2-4) CSR build on forked stream (scan also zeroes BN stats/counters)
    hist_kernel<<<(E + 255) / 256, 256, 0, sb>>>(edge_rows, E);
    scan_kernel<<<1, 1024, 0, sb>>>();
    scatter_kernel<<<(E + 255) / 256, 256, 0, sb>>>(edge_rows, edge_cols, edge_vals, E);

    const dim3 gmain(H_DIM / 128, (N_NODES + 127) / 128);
    const int  spmm_blocks = (N_NODES + 31) / 32;

    // (5) layer 1 GEMM overlaps CSR build
    hgemm<256, false, false, true, true, float><<<gmain, 256>>>(
        features, w1h, db1, hH, N_NODES, nullptr, nullptr, nullptr);

    if (forked) {
        cudaEventRecord(eJoin, s2);
        cudaStreamWaitEvent(0, eJoin, 0);
    }

    // (6) layer 1 aggregate + BN stats + finalize -> a1,c1
    spmm_stats_kernel<0><<<spmm_blocks, 256>>>(hH, yH, g1, be1, a1, c1);

    // (7) layer 2 GEMM (BN fused into A path)
    hgemm<256, true, false, false, true, __half><<<gmain, 256>>>(
        yH, w2h, nullptr, hH, N_NODES, nullptr, a1, c1);

    // (8) layer 2 aggregate + BN stats + finalize -> a2,c2
    spmm_stats_kernel<1><<<spmm_blocks, 256>>>(hH, yH, g2, be2, a2, c2);

    // (9) head: out = relu(bn2(yH))[idx] @ Wf + bf  (fp32 out)
    const dim3 ghead(1, (Mi + 127) / 128);
    hgemm<128, true, true, true, false, __half><<<ghead, 256>>>(
        yH, wfh, bf, out, Mi, idx, a2, c2);

    if (forked) {
        cudaStreamDestroy(s2);
        cudaEventDestroy(eFork);
        cudaEventDestroy(eJoin);
    }
}